// round 13
// baseline (speedup 1.0000x reference)
#include <cuda_runtime.h>

// Fixed problem shape — kernel_launch is a pure function of the data pointers.
#define N_NODES 100000
#define N_EDGES 1600000
#define DIM     128
#define D4      32
#define TILE_M  32          // nodes per GEMM block
#define KCHUNK  32          // K rows of W staged per smem chunk
#define OUTD    5
#define SA_S    36          // sA row stride in words (padded, 16B-aligned)
#define SCAN_T  1024
#define CHUNK   98          // ceil(N_NODES / SCAN_T)
#define HIST_BLOCKS 6250    // (N_EDGES+255)/256
#define GEMM_BLOCKS 3125    // N_NODES / TILE_M

// ---------------- scratch (device globals; referenced ONLY in device code!) ----
// Passing these symbols as host-side kernel args would pass the HOST shadow
// (reachable via ATS on GB300) -> wrong buffer. Device-code refs only.
__device__ __align__(16) float g_y [(size_t)N_NODES * DIM];   // x @ W1
__device__ __align__(16) float g_z2[(size_t)N_NODES * DIM];   // h1 @ W2
__device__ int g_cnt[N_NODES];          // degree histogram
__device__ int g_off[N_NODES + 1];      // CSR row offsets (by target)
__device__ int g_cur[N_NODES];          // fill cursors
__device__ int g_csr[N_EDGES];          // src ids grouped by target

// ---------------- zero degree histogram ----------------
__global__ void __launch_bounds__(256) zero_cnt_kernel() {
    int i = blockIdx.x * 256 + threadIdx.x;
    if (i < N_NODES) g_cnt[i] = 0;
}

// ---------------- one-block exclusive scan -> g_off, g_cur ----------------
__global__ void __launch_bounds__(SCAN_T) scan_kernel() {
    __shared__ int ssum[SCAN_T];
    int t  = threadIdx.x;
    int lo = t * CHUNK;
    int hi = lo + CHUNK; if (hi > N_NODES) hi = N_NODES;
    int s = 0;
    for (int i = lo; i < hi; i++) s += g_cnt[i];
    ssum[t] = s;
    __syncthreads();
    for (int d = 1; d < SCAN_T; d <<= 1) {
        int other = (t >= d) ? ssum[t - d] : 0;
        __syncthreads();
        ssum[t] += other;
        __syncthreads();
    }
    int run = ssum[t] - s;
    for (int i = lo; i < hi; i++) {
        int c = g_cnt[i];
        g_off[i] = run;
        g_cur[i] = run;
        run += c;
    }
    if (t == SCAN_T - 1) g_off[N_NODES] = ssum[SCAN_T - 1];
}

// ---------------- permute src ids into CSR order ----------------
__global__ void __launch_bounds__(256) fill_kernel(
    const int* __restrict__ src, const int* __restrict__ tgt) {
    int e = blockIdx.x * 256 + threadIdx.x;
    if (e < N_EDGES) {
        int p = atomicAdd(&g_cur[__ldg(tgt + e)], 1);
        g_csr[p] = __ldg(src + e);
    }
}

// ================= K2: mega kernel — hist blocks ∥ dense GEMM y = x@W1 =======
// First HIST_BLOCKS blocks: degree histogram (hidden behind the GEMM's FMA).
// Remaining GEMM_BLOCKS: y = x @ W1 (no bias/relu), register-tiled 32mx128n.
__global__ void __launch_bounds__(256) mega_kernel(
    const float* __restrict__ x,
    const int*   __restrict__ tgt,
    const float* __restrict__ W)
{
    __shared__ __align__(16) float sA[DIM * SA_S];     // [k][m], 18 KB
    __shared__ __align__(16) float sW[KCHUNK * DIM];   // [k][n], 16 KB

    if (blockIdx.x < HIST_BLOCKS) {
        int e = blockIdx.x * 256 + threadIdx.x;
        if (e < N_EDGES) atomicAdd(&g_cnt[__ldg(tgt + e)], 1);
        return;
    }

    int row0 = (blockIdx.x - HIST_BLOCKS) * TILE_M;
    int lane = threadIdx.x & 31;
    int w    = threadIdx.x >> 5;

    // transpose x tile into sA[k][m] (warp w -> rows 4w..4w+3)
    #pragma unroll
    for (int j = 0; j < 4; j++) {
        int m = w * 4 + j;
        const float* row = x + (size_t)(row0 + m) * DIM;
        sA[(lane     ) * SA_S + m] = __ldg(row + lane     );
        sA[(lane + 32) * SA_S + m] = __ldg(row + lane + 32);
        sA[(lane + 64) * SA_S + m] = __ldg(row + lane + 64);
        sA[(lane + 96) * SA_S + m] = __ldg(row + lane + 96);
    }

    int mg = lane >> 3, ng = lane & 7;
    int wm = w & 1, wn = w >> 1;
    int mbase = wm * 16 + mg * 4;
    int nbase = wn * 32 + ng * 4;

    float acc[4][4];
    #pragma unroll
    for (int ii = 0; ii < 4; ii++)
        #pragma unroll
        for (int jj = 0; jj < 4; jj++) acc[ii][jj] = 0.f;

    #pragma unroll 1
    for (int kc = 0; kc < DIM / KCHUNK; kc++) {
        __syncthreads();
        const float4* Wsrc = reinterpret_cast<const float4*>(W + kc * KCHUNK * DIM);
        float4* sW4 = reinterpret_cast<float4*>(sW);
        #pragma unroll
        for (int i = threadIdx.x; i < KCHUNK * D4; i += 256) sW4[i] = Wsrc[i];
        __syncthreads();

        const float* aptr = sA + (kc * KCHUNK) * SA_S + mbase;
        const float* wptr = sW + nbase;
        #pragma unroll 4
        for (int k = 0; k < KCHUNK; k++) {
            float4 av = *reinterpret_cast<const float4*>(aptr);
            float4 wv = *reinterpret_cast<const float4*>(wptr);
            acc[0][0] = fmaf(av.x, wv.x, acc[0][0]);
            acc[0][1] = fmaf(av.x, wv.y, acc[0][1]);
            acc[0][2] = fmaf(av.x, wv.z, acc[0][2]);
            acc[0][3] = fmaf(av.x, wv.w, acc[0][3]);
            acc[1][0] = fmaf(av.y, wv.x, acc[1][0]);
            acc[1][1] = fmaf(av.y, wv.y, acc[1][1]);
            acc[1][2] = fmaf(av.y, wv.z, acc[1][2]);
            acc[1][3] = fmaf(av.y, wv.w, acc[1][3]);
            acc[2][0] = fmaf(av.z, wv.x, acc[2][0]);
            acc[2][1] = fmaf(av.z, wv.y, acc[2][1]);
            acc[2][2] = fmaf(av.z, wv.z, acc[2][2]);
            acc[2][3] = fmaf(av.z, wv.w, acc[2][3]);
            acc[3][0] = fmaf(av.w, wv.x, acc[3][0]);
            acc[3][1] = fmaf(av.w, wv.y, acc[3][1]);
            acc[3][2] = fmaf(av.w, wv.z, acc[3][2]);
            acc[3][3] = fmaf(av.w, wv.w, acc[3][3]);
            aptr += SA_S;
            wptr += DIM;
        }
    }

    #pragma unroll
    for (int ii = 0; ii < 4; ii++) {
        int node = row0 + mbase + ii;
        *reinterpret_cast<float4*>(g_y + (size_t)node * DIM + nbase) =
            make_float4(acc[ii][0], acc[ii][1], acc[ii][2], acc[ii][3]);
    }
}

// ================= K5: fused mid layer ======================================
// gather agg(y) -> h1 = relu(y + agg + b1) into sA -> z2 = h1 @ W2 -> g_z2.
__global__ void __launch_bounds__(256) fused_mid_kernel(
    const float* __restrict__ b1,
    const float* __restrict__ W)
{
    __shared__ __align__(16) float sA[DIM * SA_S];     // h1 tile [k][m]
    __shared__ __align__(16) float sW[KCHUNK * DIM];

    const float* feat = (const float*)g_y;
    int row0 = blockIdx.x * TILE_M;
    int lane = threadIdx.x & 31;
    int w    = threadIdx.x >> 5;

    float b1r0 = __ldg(b1 + lane);
    float b1r1 = __ldg(b1 + lane + 32);
    float b1r2 = __ldg(b1 + lane + 64);
    float b1r3 = __ldg(b1 + lane + 96);

    // ---------- gather phase: 4 nodes per warp, 4-edge unroll ----------
    #pragma unroll 1
    for (int j = 0; j < 4; j++) {
        int m    = w * 4 + j;
        int node = row0 + m;
        int beg  = g_off[node];
        int end  = g_off[node + 1];

        float a0 = 0.f, a1 = 0.f, a2 = 0.f, a3 = 0.f;
        int i = beg;
        for (; i + 4 <= end; i += 4) {            // 16 loads in flight
            const float* r0 = feat + (size_t)__ldg(g_csr + i    ) * DIM;
            const float* r1 = feat + (size_t)__ldg(g_csr + i + 1) * DIM;
            const float* r2 = feat + (size_t)__ldg(g_csr + i + 2) * DIM;
            const float* r3 = feat + (size_t)__ldg(g_csr + i + 3) * DIM;
            float t00 = __ldg(r0 + lane),      t01 = __ldg(r0 + lane + 32);
            float t02 = __ldg(r0 + lane + 64), t03 = __ldg(r0 + lane + 96);
            float t10 = __ldg(r1 + lane),      t11 = __ldg(r1 + lane + 32);
            float t12 = __ldg(r1 + lane + 64), t13 = __ldg(r1 + lane + 96);
            float t20 = __ldg(r2 + lane),      t21 = __ldg(r2 + lane + 32);
            float t22 = __ldg(r2 + lane + 64), t23 = __ldg(r2 + lane + 96);
            float t30 = __ldg(r3 + lane),      t31 = __ldg(r3 + lane + 32);
            float t32 = __ldg(r3 + lane + 64), t33 = __ldg(r3 + lane + 96);
            a0 += (t00 + t10) + (t20 + t30);
            a1 += (t01 + t11) + (t21 + t31);
            a2 += (t02 + t12) + (t22 + t32);
            a3 += (t03 + t13) + (t23 + t33);
        }
        for (; i < end; i++) {
            const float* r0 = feat + (size_t)__ldg(g_csr + i) * DIM;
            a0 += __ldg(r0 + lane);      a1 += __ldg(r0 + lane + 32);
            a2 += __ldg(r0 + lane + 64); a3 += __ldg(r0 + lane + 96);
        }

        int d = end - beg;
        float inv = 1.0f / (float)(d < 1 ? 1 : d);
        const float* base = feat + (size_t)node * DIM;
        sA[(lane     ) * SA_S + m] = fmaxf(fmaf(a0, inv, __ldg(base + lane     )) + b1r0, 0.f);
        sA[(lane + 32) * SA_S + m] = fmaxf(fmaf(a1, inv, __ldg(base + lane + 32)) + b1r1, 0.f);
        sA[(lane + 64) * SA_S + m] = fmaxf(fmaf(a2, inv, __ldg(base + lane + 64)) + b1r2, 0.f);
        sA[(lane + 96) * SA_S + m] = fmaxf(fmaf(a3, inv, __ldg(base + lane + 96)) + b1r3, 0.f);
    }

    // ---------- GEMM: z2 = h1 @ W2 (raw, bias added later) ----------
    int mg = lane >> 3, ng = lane & 7;
    int wm = w & 1, wn = w >> 1;
    int mbase = wm * 16 + mg * 4;
    int nbase = wn * 32 + ng * 4;

    float acc[4][4];
    #pragma unroll
    for (int ii = 0; ii < 4; ii++)
        #pragma unroll
        for (int jj = 0; jj < 4; jj++) acc[ii][jj] = 0.f;

    #pragma unroll 1
    for (int kc = 0; kc < DIM / KCHUNK; kc++) {
        __syncthreads();
        const float4* Wsrc = reinterpret_cast<const float4*>(W + kc * KCHUNK * DIM);
        float4* sW4 = reinterpret_cast<float4*>(sW);
        #pragma unroll
        for (int i = threadIdx.x; i < KCHUNK * D4; i += 256) sW4[i] = Wsrc[i];
        __syncthreads();

        const float* aptr = sA + (kc * KCHUNK) * SA_S + mbase;
        const float* wptr = sW + nbase;
        #pragma unroll 4
        for (int k = 0; k < KCHUNK; k++) {
            float4 av = *reinterpret_cast<const float4*>(aptr);
            float4 wv = *reinterpret_cast<const float4*>(wptr);
            acc[0][0] = fmaf(av.x, wv.x, acc[0][0]);
            acc[0][1] = fmaf(av.x, wv.y, acc[0][1]);
            acc[0][2] = fmaf(av.x, wv.z, acc[0][2]);
            acc[0][3] = fmaf(av.x, wv.w, acc[0][3]);
            acc[1][0] = fmaf(av.y, wv.x, acc[1][0]);
            acc[1][1] = fmaf(av.y, wv.y, acc[1][1]);
            acc[1][2] = fmaf(av.y, wv.z, acc[1][2]);
            acc[1][3] = fmaf(av.y, wv.w, acc[1][3]);
            acc[2][0] = fmaf(av.z, wv.x, acc[2][0]);
            acc[2][1] = fmaf(av.z, wv.y, acc[2][1]);
            acc[2][2] = fmaf(av.z, wv.z, acc[2][2]);
            acc[2][3] = fmaf(av.z, wv.w, acc[2][3]);
            acc[3][0] = fmaf(av.w, wv.x, acc[3][0]);
            acc[3][1] = fmaf(av.w, wv.y, acc[3][1]);
            acc[3][2] = fmaf(av.w, wv.z, acc[3][2]);
            acc[3][3] = fmaf(av.w, wv.w, acc[3][3]);
            aptr += SA_S;
            wptr += DIM;
        }
    }

    #pragma unroll
    for (int ii = 0; ii < 4; ii++) {
        int node = row0 + mbase + ii;
        *reinterpret_cast<float4*>(g_z2 + (size_t)node * DIM + nbase) =
            make_float4(acc[ii][0], acc[ii][1], acc[ii][2], acc[ii][3]);
    }
}

// ================= K6: gather agg(z2) + relu + projection ===================
// warp-per-node: h2 = relu(z2 + agg(z2) + b2) in registers; out = h2@Wp + bp.
__global__ void __launch_bounds__(256) out_kernel(
    const float* __restrict__ b2,
    const float* __restrict__ Wp,
    const float* __restrict__ bp,
    float*       __restrict__ out)
{
    __shared__ float sWp[DIM * OUTD];               // 2.5 KB
    for (int i = threadIdx.x; i < DIM * OUTD; i += 256) sWp[i] = __ldg(Wp + i);
    __syncthreads();

    int node = (blockIdx.x * 256 + threadIdx.x) >> 5;   // 12500 blocks * 8 = 100000
    int lane = threadIdx.x & 31;
    const float* feat = (const float*)g_z2;

    int beg = g_off[node];
    int end = g_off[node + 1];

    float a0 = 0.f, a1 = 0.f, a2 = 0.f, a3 = 0.f;
    int i = beg;
    for (; i + 4 <= end; i += 4) {
        const float* r0 = feat + (size_t)__ldg(g_csr + i    ) * DIM;
        const float* r1 = feat + (size_t)__ldg(g_csr + i + 1) * DIM;
        const float* r2 = feat + (size_t)__ldg(g_csr + i + 2) * DIM;
        const float* r3 = feat + (size_t)__ldg(g_csr + i + 3) * DIM;
        float t00 = __ldg(r0 + lane),      t01 = __ldg(r0 + lane + 32);
        float t02 = __ldg(r0 + lane + 64), t03 = __ldg(r0 + lane + 96);
        float t10 = __ldg(r1 + lane),      t11 = __ldg(r1 + lane + 32);
        float t12 = __ldg(r1 + lane + 64), t13 = __ldg(r1 + lane + 96);
        float t20 = __ldg(r2 + lane),      t21 = __ldg(r2 + lane + 32);
        float t22 = __ldg(r2 + lane + 64), t23 = __ldg(r2 + lane + 96);
        float t30 = __ldg(r3 + lane),      t31 = __ldg(r3 + lane + 32);
        float t32 = __ldg(r3 + lane + 64), t33 = __ldg(r3 + lane + 96);
        a0 += (t00 + t10) + (t20 + t30);
        a1 += (t01 + t11) + (t21 + t31);
        a2 += (t02 + t12) + (t22 + t32);
        a3 += (t03 + t13) + (t23 + t33);
    }
    for (; i < end; i++) {
        const float* r0 = feat + (size_t)__ldg(g_csr + i) * DIM;
        a0 += __ldg(r0 + lane);      a1 += __ldg(r0 + lane + 32);
        a2 += __ldg(r0 + lane + 64); a3 += __ldg(r0 + lane + 96);
    }

    int d = end - beg;
    float inv = 1.0f / (float)(d < 1 ? 1 : d);
    const float* base = feat + (size_t)node * DIM;
    float h0 = fmaxf(fmaf(a0, inv, __ldg(base + lane     )) + __ldg(b2 + lane     ), 0.f);
    float h1 = fmaxf(fmaf(a1, inv, __ldg(base + lane + 32)) + __ldg(b2 + lane + 32), 0.f);
    float h2 = fmaxf(fmaf(a2, inv, __ldg(base + lane + 64)) + __ldg(b2 + lane + 64), 0.f);
    float h3 = fmaxf(fmaf(a3, inv, __ldg(base + lane + 96)) + __ldg(b2 + lane + 96), 0.f);

    float s[OUTD];
    #pragma unroll
    for (int j = 0; j < OUTD; j++) {
        s[j] = h0 * sWp[(lane     ) * OUTD + j]
             + h1 * sWp[(lane + 32) * OUTD + j]
             + h2 * sWp[(lane + 64) * OUTD + j]
             + h3 * sWp[(lane + 96) * OUTD + j];
    }
    #pragma unroll
    for (int o = 16; o > 0; o >>= 1) {
        #pragma unroll
        for (int j = 0; j < OUTD; j++)
            s[j] += __shfl_xor_sync(0xffffffff, s[j], o);
    }
    if (lane < OUTD)
        out[(size_t)node * OUTD + lane] = s[lane] + __ldg(bp + lane);
}

// ---------------- launch (kernel launches ONLY; pure function of pointers) ----
extern "C" void kernel_launch(void* const* d_in, const int* in_sizes, int n_in,
                              void* d_out, int out_size)
{
    (void)in_sizes; (void)n_in; (void)out_size;   // fixed-shape problem

    const float* x   = (const float*)d_in[0];
    const int* edges = (const int*)  d_in[1];
    const float* W1  = (const float*)d_in[2];
    const float* b1  = (const float*)d_in[3];
    const float* W2  = (const float*)d_in[4];
    const float* b2  = (const float*)d_in[5];
    const float* Wp  = (const float*)d_in[6];
    const float* bp  = (const float*)d_in[7];
    float* out = (float*)d_out;

    const int* src = edges;                 // edges[0, :]
    const int* tgt = edges + N_EDGES;       // edges[1, :]

    zero_cnt_kernel<<<(N_NODES + 255) / 256, 256>>>();
    mega_kernel<<<HIST_BLOCKS + GEMM_BLOCKS, 256>>>(x, tgt, W1);
    scan_kernel<<<1, SCAN_T>>>();
    fill_kernel<<<HIST_BLOCKS, 256>>>(src, tgt);
    fused_mid_kernel<<<GEMM_BLOCKS, 256>>>(b1, W2);
    out_kernel<<<N_NODES / 8, 256>>>(b2, Wp, bp, out);
}